// round 9
// baseline (speedup 1.0000x reference)
#include <cuda_runtime.h>

namespace {

constexpr int BATCH   = 4;
constexpr int NIN     = 1024;
constexpr int NOUT    = 1024;
constexpr int CH      = 8;     // density + 7 raw channels
constexpr int OC      = 16;
constexpr int OPB     = 64;    // outputs per block (2 per lane)
constexpr int SPLITS  = 8;     // i-dimension splits across blocks
constexpr int ISPB    = NIN / SPLITS;      // 128 i per block
constexpr int THREADS = 256;
constexpr int WARPS   = THREADS / 32;      // 8
constexpr int IPW     = ISPB / WARPS;      // 16 i per warp
constexpr int NTILES  = NOUT / OPB;        // 16 otiles

// Partial aggregates: [b*1024+O][split][c]  (1 MB scratch)
__device__ float g_part[BATCH * NOUT * SPLITS * CH];
// Per-otile completion counters (zero-init; finisher resets -> replay-safe)
__device__ int   g_count[BATCH * NTILES];

__device__ __forceinline__ float ex2_approx(float x) {
    float y;
    asm("ex2.approx.f32 %0, %1;" : "=f"(y) : "f"(x));
    return y;
}

// Packed dual-FMA: acc.{lo,hi} += y.{lo,hi} * m.{lo,hi}
__device__ __forceinline__ void ffma2(unsigned long long& acc,
                                      unsigned long long y,
                                      unsigned long long m) {
    asm("fma.rn.f32x2 %0, %1, %2, %0;" : "+l"(acc) : "l"(y), "l"(m));
}

__device__ __forceinline__ unsigned long long pack2(float w) {
    unsigned long long r;
    asm("mov.b64 %0, {%1, %1};" : "=l"(r) : "f"(w));
    return r;
}

__device__ __forceinline__ float2 unpack2(unsigned long long v) {
    float2 f;
    asm("mov.b64 {%0, %1}, %2;" : "=f"(f.x), "=f"(f.y) : "l"(v));
    return f;
}

// --------- Fused kernel: partial aggregation + last-block finish ---------
__global__ __launch_bounds__(THREADS, 4)
void convdeepset_kernel(const float* __restrict__ cx,     // [B, NIN, 1]
                        const float* __restrict__ cy,     // [B, NIN, 7]
                        const float* __restrict__ t,      // [B, NOUT, 1]
                        const float* __restrict__ sigma,  // [8]
                        const float* __restrict__ W,      // [8, 16]
                        const float* __restrict__ bias,   // [16]
                        float* __restrict__ out)          // [B*NOUT, 16]
{
    // sy[i] = [y1..y7, 1.0] -> two LDS.128 give 4 natural f32x2 pairs
    __shared__ float  sy[ISPB][CH];              // 4 KB
    __shared__ float  sx[ISPB];                  // 0.5 KB (pre-scaled x)
    __shared__ float  spart[WARPS][OPB][CH];     // 16 KB
    __shared__ float  sbeta[CH];
    __shared__ float  sagg2[OPB][CH];            // 2 KB (finisher only)
    __shared__ int    s_last;

    const int bi    = blockIdx.x;
    const int b     = bi >> 7;                   // / (NTILES*SPLITS)
    const int otile = (bi >> 3) & 15;
    const int split = bi & 7;
    const int tid   = threadIdx.x;
    const int warp  = tid >> 5;
    const int lane  = tid & 31;
    const int i0    = split * ISPB;

    if (tid < CH) {
        float s = expf(sigma[tid]);
        sbeta[tid] = -0.5f * 1.4426950408889634f / (s * s);
    }

    // k = sqrt(-beta0): every thread computes (beta0 < 0 always)
    float s0 = expf(sigma[0]);
    const float kscale = sqrtf(0.5f * 1.4426950408889634f) / s0;

    // Stage y channels with density=1.0 in slot 7 (4 iters/thread)
    #pragma unroll
    for (int r = 0; r < 4; r++) {
        int idx = tid + r * THREADS;             // 0..1023
        int i = idx >> 3, c = idx & 7;
        sy[i][c] = (c < 7) ? cy[(b * NIN + i0 + i) * 7 + c] : 1.0f;
    }
    // Stage pre-scaled x
    if (tid < ISPB) sx[tid] = kscale * cx[b * NIN + i0 + tid];

    const int G0 = b * NOUT + otile * OPB;
    const float t0 = kscale * t[G0 + lane];
    const float t1 = kscale * t[G0 + 32 + lane];
    __syncthreads();

    const float beta0 = sbeta[0];
    bool uni = true;
    #pragma unroll
    for (int c = 1; c < CH; c++) uni &= (sbeta[c] == beta0);

    // Canonical per-channel results for both outputs: [den, y1..y7]
    float r0c[CH], r1c[CH];

    const float*     xw = &sx[warp * IPW];
    const longlong2* yw = reinterpret_cast<const longlong2*>(&sy[warp * IPW][0]);

    if (uni) {
        unsigned long long a12_0 = 0, a34_0 = 0, a56_0 = 0, a7d_0 = 0;
        unsigned long long a12_1 = 0, a34_1 = 0, a56_1 = 0, a7d_1 = 0;
        #pragma unroll 4
        for (int j = 0; j < IPW; j++) {
            float x = xw[j];                     // broadcast LDS
            float d0 = x - t0;
            float d1 = x - t1;
            float w0 = ex2_approx(-(d0 * d0));
            float w1 = ex2_approx(-(d1 * d1));
            longlong2 p0 = yw[2 * j];            // {y1,y2},{y3,y4} (broadcast)
            longlong2 p1 = yw[2 * j + 1];        // {y5,y6},{y7,1}
            unsigned long long ww0 = pack2(w0);
            unsigned long long ww1 = pack2(w1);
            ffma2(a12_0, (unsigned long long)p0.x, ww0);
            ffma2(a34_0, (unsigned long long)p0.y, ww0);
            ffma2(a56_0, (unsigned long long)p1.x, ww0);
            ffma2(a7d_0, (unsigned long long)p1.y, ww0);
            ffma2(a12_1, (unsigned long long)p0.x, ww1);
            ffma2(a34_1, (unsigned long long)p0.y, ww1);
            ffma2(a56_1, (unsigned long long)p1.x, ww1);
            ffma2(a7d_1, (unsigned long long)p1.y, ww1);
        }
        {
            float2 u12 = unpack2(a12_0), u34 = unpack2(a34_0);
            float2 u56 = unpack2(a56_0), u7d = unpack2(a7d_0);
            r0c[0] = u7d.y;
            r0c[1] = u12.x; r0c[2] = u12.y; r0c[3] = u34.x; r0c[4] = u34.y;
            r0c[5] = u56.x; r0c[6] = u56.y; r0c[7] = u7d.x;
        }
        {
            float2 u12 = unpack2(a12_1), u34 = unpack2(a34_1);
            float2 u56 = unpack2(a56_1), u7d = unpack2(a7d_1);
            r1c[0] = u7d.y;
            r1c[1] = u12.x; r1c[2] = u12.y; r1c[3] = u34.x; r1c[4] = u34.y;
            r1c[5] = u56.x; r1c[6] = u56.y; r1c[7] = u7d.x;
        }
    } else {
        // General path: a_c = (beta_c/beta0) * a, a = beta0*d2
        float ratio[CH];
        #pragma unroll
        for (int c = 0; c < CH; c++) ratio[c] = sbeta[c] / beta0;
        #pragma unroll
        for (int c = 0; c < CH; c++) { r0c[c] = 0.0f; r1c[c] = 0.0f; }
        const float* yws = &sy[warp * IPW][0];
        for (int j = 0; j < IPW; j++) {
            float x = xw[j];
            float d0 = x - t0, d1 = x - t1;
            float a0 = -(d0 * d0), a1 = -(d1 * d1);
            r0c[0] += ex2_approx(ratio[0] * a0);
            r1c[0] += ex2_approx(ratio[0] * a1);
            #pragma unroll
            for (int c = 1; c < CH; c++) {
                float yv = yws[j * CH + (c - 1)];
                r0c[c] += yv * ex2_approx(ratio[c] * a0);
                r1c[c] += yv * ex2_approx(ratio[c] * a1);
            }
        }
    }

    // Per-warp partials for both owned outputs
    *reinterpret_cast<float4*>(&spart[warp][lane][0]) =
        make_float4(r0c[0], r0c[1], r0c[2], r0c[3]);
    *reinterpret_cast<float4*>(&spart[warp][lane][4]) =
        make_float4(r0c[4], r0c[5], r0c[6], r0c[7]);
    *reinterpret_cast<float4*>(&spart[warp][32 + lane][0]) =
        make_float4(r1c[0], r1c[1], r1c[2], r1c[3]);
    *reinterpret_cast<float4*>(&spart[warp][32 + lane][4]) =
        make_float4(r1c[4], r1c[5], r1c[6], r1c[7]);
    __syncthreads();

    // Cross-warp reduce: 512 (o,c) slots over 256 threads (2 each)
    #pragma unroll
    for (int rr = 0; rr < 2; rr++) {
        int idx = tid + rr * THREADS;
        int o = idx >> 3, c = idx & 7;
        float s = 0.0f;
        #pragma unroll
        for (int w2 = 0; w2 < WARPS; w2++) s += spart[w2][o][c];
        g_part[((G0 + o) * SPLITS + split) * CH + c] = s;
    }

    // ---- last-block-done gate (threadFenceReduction pattern) ----
    __threadfence();
    if (tid == 0) {
        int old = atomicAdd(&g_count[b * NTILES + otile], 1);
        s_last = (old == SPLITS - 1);
        if (s_last) g_count[b * NTILES + otile] = 0;   // reset for replay
    }
    __syncthreads();
    if (!s_last) return;

    // ---- finish: combine splits + normalize (2 slots per thread) ----
    #pragma unroll
    for (int rr = 0; rr < 2; rr++) {
        int idx = tid + rr * THREADS;
        int o = idx >> 3, c = idx & 7;
        const float* p = &g_part[((G0 + o) * SPLITS) * CH + c];
        float s = 0.0f;
        #pragma unroll
        for (int sp = 0; sp < SPLITS; sp++) s += p[sp * CH];
        float den = __shfl_sync(0xffffffffu, s, lane & ~7u);
        sagg2[o][c] = (c == 0) ? s : s / (den + 1e-8f);
    }
    __syncthreads();

    // ---- finish: out[G][k] = bias[k] + sum_c agg2[c] * W[c][k] ----
    #pragma unroll
    for (int rr = 0; rr < 4; rr++) {
        int idx = tid + rr * THREADS;                 // 0..1023
        int o = idx >> 4, k = idx & 15;
        float v = __ldg(&bias[k]);
        #pragma unroll
        for (int c = 0; c < CH; c++) v += sagg2[o][c] * __ldg(&W[c * OC + k]);
        out[(G0 + o) * OC + k] = v;                   // coalesced
    }
}

} // namespace

extern "C" void kernel_launch(void* const* d_in, const int* in_sizes, int n_in,
                              void* d_out, int out_size) {
    const float* cx = (const float*)d_in[0];  // context_x
    const float* cy = (const float*)d_in[1];  // context_y
    const float* t  = (const float*)d_in[2];  // t
    const float* sg = (const float*)d_in[3];  // sigma
    const float* W  = (const float*)d_in[4];  // W
    const float* bi = (const float*)d_in[5];  // b
    float* out = (float*)d_out;

    convdeepset_kernel<<<BATCH * NTILES * SPLITS, THREADS>>>(cx, cy, t, sg, W, bi, out);
}

// round 10
// speedup vs baseline: 1.1327x; 1.1327x over previous
#include <cuda_runtime.h>

namespace {

constexpr int BATCH   = 4;
constexpr int NIN     = 1024;
constexpr int NOUT    = 1024;
constexpr int CH      = 8;     // density + 7 raw channels
constexpr int OC      = 16;
constexpr int OPB     = 32;    // outputs per block (= warp width)
constexpr int SPLITS  = 4;     // i-dimension splits across blocks
constexpr int ISPB    = NIN / SPLITS;      // 256 i per block
constexpr int THREADS = 256;
constexpr int WARPS   = THREADS / 32;      // 8
constexpr int IPW     = ISPB / WARPS;      // 32 i per warp

// Partial aggregates: [b*1024+O][split][c]  (512 KB scratch)
__device__ float g_part[BATCH * NOUT * SPLITS * CH];
// Per-otile completion counters (zero-init; finisher resets -> replay-safe)
__device__ int   g_count[BATCH * 32];

__device__ __forceinline__ float ex2_approx(float x) {
    float y;
    asm("ex2.approx.f32 %0, %1;" : "=f"(y) : "f"(x));
    return y;
}

// Packed dual-FMA: acc.{lo,hi} += y.{lo,hi} * m.{lo,hi}
__device__ __forceinline__ void ffma2(unsigned long long& acc,
                                      unsigned long long y,
                                      unsigned long long m) {
    asm("fma.rn.f32x2 %0, %1, %2, %0;" : "+l"(acc) : "l"(y), "l"(m));
}

__device__ __forceinline__ unsigned long long pack2(float w) {
    unsigned long long r;
    asm("mov.b64 %0, {%1, %1};" : "=l"(r) : "f"(w));
    return r;
}

__device__ __forceinline__ float2 unpack2(unsigned long long v) {
    float2 f;
    asm("mov.b64 {%0, %1}, %2;" : "=f"(f.x), "=f"(f.y) : "l"(v));
    return f;
}

// --------- Fused kernel: partial aggregation + last-block finish ---------
// (256, 5): 51-reg budget -> ~40 warps/SM target (between R6's 42 and R8's 64)
__global__ __launch_bounds__(THREADS, 5)
void convdeepset_kernel(const float* __restrict__ cx,     // [B, NIN, 1]
                        const float* __restrict__ cy,     // [B, NIN, 7]
                        const float* __restrict__ t,      // [B, NOUT, 1]
                        const float* __restrict__ sigma,  // [8]
                        const float* __restrict__ W,      // [8, 16]
                        const float* __restrict__ bias,   // [16]
                        float* __restrict__ out)          // [B*NOUT, 16]
{
    // sy[i] = [y1..y7, 1.0] -> two LDS.128 give 4 natural f32x2 pairs
    __shared__ float  sy[ISPB][CH];              // 8 KB
    __shared__ float  sx[ISPB];                  // 1 KB (pre-scaled x)
    __shared__ float  spart[WARPS][OPB][CH];     // 8 KB
    __shared__ float  sbeta[CH];
    __shared__ float  sagg2[OPB][CH];            // 1 KB (finisher only)
    __shared__ int    s_last;

    const int bi    = blockIdx.x;
    const int b     = bi >> 7;                   // / (32*4)
    const int otile = (bi >> 2) & 31;
    const int split = bi & 3;
    const int tid   = threadIdx.x;
    const int warp  = tid >> 5;
    const int lane  = tid & 31;
    const int i0    = split * ISPB;

    if (tid < CH) {
        float s = expf(sigma[tid]);
        sbeta[tid] = -0.5f * 1.4426950408889634f / (s * s);
    }

    // k = sqrt(-beta0): every thread computes (beta0 < 0 always)
    float s0 = expf(sigma[0]);
    const float kscale = sqrtf(0.5f * 1.4426950408889634f) / s0;

    // Stage y channels with density=1.0 in slot 7
    #pragma unroll
    for (int r = 0; r < 8; r++) {
        int idx = tid + r * THREADS;             // 0..2047
        int i = idx >> 3, c = idx & 7;
        sy[i][c] = (c < 7) ? cy[(b * NIN + i0 + i) * 7 + c] : 1.0f;
    }
    // Stage pre-scaled x (256 threads, 1 element each)
    sx[tid] = kscale * cx[b * NIN + i0 + tid];

    const float t_k = kscale * t[b * NOUT + otile * OPB + lane];
    __syncthreads();

    const float beta0 = sbeta[0];
    bool uni = true;
    #pragma unroll
    for (int c = 1; c < CH; c++) uni &= (sbeta[c] == beta0);

    // Canonical per-channel results: [den, y1..y7]
    float r_can[CH];

    const float*     xw = &sx[warp * IPW];
    const longlong2* yw = reinterpret_cast<const longlong2*>(&sy[warp * IPW][0]);

    if (uni) {
        unsigned long long a12 = 0, a34 = 0, a56 = 0, a7d = 0;
        #pragma unroll 4
        for (int j = 0; j < IPW; j++) {
            float d = xw[j] - t_k;               // scaled distance
            float w = ex2_approx(-(d * d));      // exp2(beta0 * d2)
            longlong2 p0 = yw[2 * j];            // {y1,y2},{y3,y4}  (broadcast)
            longlong2 p1 = yw[2 * j + 1];        // {y5,y6},{y7,1}
            unsigned long long ww = pack2(w);
            ffma2(a12, (unsigned long long)p0.x, ww);
            ffma2(a34, (unsigned long long)p0.y, ww);
            ffma2(a56, (unsigned long long)p1.x, ww);
            ffma2(a7d, (unsigned long long)p1.y, ww);
        }
        float2 u12 = unpack2(a12), u34 = unpack2(a34);
        float2 u56 = unpack2(a56), u7d = unpack2(a7d);
        r_can[0] = u7d.y;                        // density
        r_can[1] = u12.x; r_can[2] = u12.y;
        r_can[3] = u34.x; r_can[4] = u34.y;
        r_can[5] = u56.x; r_can[6] = u56.y;
        r_can[7] = u7d.x;
    } else {
        // ratios: a_c = (beta_c/beta0) * a, where a = beta0*d2
        float ratio[CH];
        #pragma unroll
        for (int c = 0; c < CH; c++) ratio[c] = sbeta[c] / beta0;
        float acc[CH];
        #pragma unroll
        for (int c = 0; c < CH; c++) acc[c] = 0.0f;
        const float* yws = &sy[warp * IPW][0];
        #pragma unroll 2
        for (int j = 0; j < IPW; j++) {
            float d = xw[j] - t_k;
            float a = -(d * d);                  // = beta0 * d2
            acc[0] += ex2_approx(ratio[0] * a);               // density
            #pragma unroll
            for (int c = 1; c < CH; c++)
                acc[c] += yws[j * CH + (c - 1)] * ex2_approx(ratio[c] * a);
        }
        #pragma unroll
        for (int c = 0; c < CH; c++) r_can[c] = acc[c];
    }

    // Per-warp partials (canonical order)
    *reinterpret_cast<float4*>(&spart[warp][lane][0]) =
        make_float4(r_can[0], r_can[1], r_can[2], r_can[3]);
    *reinterpret_cast<float4*>(&spart[warp][lane][4]) =
        make_float4(r_can[4], r_can[5], r_can[6], r_can[7]);
    __syncthreads();

    // Cross-warp reduce: one thread per (o, c); write partial to scratch
    const int G0 = b * NOUT + otile * OPB;
    {
        int o = tid >> 3, c = tid & 7;
        float s = 0.0f;
        #pragma unroll
        for (int w2 = 0; w2 < WARPS; w2++) s += spart[w2][o][c];
        g_part[((G0 + o) * SPLITS + split) * CH + c] = s;
    }

    // ---- last-block-done gate (threadFenceReduction pattern) ----
    __threadfence();
    if (tid == 0) {
        int old = atomicAdd(&g_count[b * 32 + otile], 1);
        s_last = (old == SPLITS - 1);
        if (s_last) g_count[b * 32 + otile] = 0;   // reset for next replay
    }
    __syncthreads();
    if (!s_last) return;

    // ---- finish: combine splits + normalize (one thread per (o, c)) ----
    {
        int o = tid >> 3, c = tid & 7;               // 32 x 8 = 256 threads
        const float* p = &g_part[((G0 + o) * SPLITS) * CH + c];
        float s = 0.0f;
        #pragma unroll
        for (int sp = 0; sp < SPLITS; sp++) s += p[sp * CH];
        float den = __shfl_sync(0xffffffffu, s, lane & ~7u);
        sagg2[o][c] = (c == 0) ? s : s / (den + 1e-8f);
    }
    __syncthreads();

    // ---- finish: out[G][k] = bias[k] + sum_c agg2[c] * W[c][k] ----
    #pragma unroll
    for (int r = 0; r < 2; r++) {
        int idx = tid + r * THREADS;                 // 0..511
        int o = idx >> 4, k = idx & 15;
        float v = __ldg(&bias[k]);
        #pragma unroll
        for (int c = 0; c < CH; c++) v += sagg2[o][c] * __ldg(&W[c * OC + k]);
        out[(G0 + o) * OC + k] = v;                  // coalesced
    }
}

} // namespace

extern "C" void kernel_launch(void* const* d_in, const int* in_sizes, int n_in,
                              void* d_out, int out_size) {
    const float* cx = (const float*)d_in[0];  // context_x
    const float* cy = (const float*)d_in[1];  // context_y
    const float* t  = (const float*)d_in[2];  // t
    const float* sg = (const float*)d_in[3];  // sigma
    const float* W  = (const float*)d_in[4];  // W
    const float* bi = (const float*)d_in[5];  // b
    float* out = (float*)d_out;

    convdeepset_kernel<<<BATCH * 32 * SPLITS, THREADS>>>(cx, cy, t, sg, W, bi, out);
}